// round 13
// baseline (speedup 1.0000x reference)
#include <cuda_runtime.h>
#include <cuda_fp16.h>
#include <cstdint>

#define NN 50000
#define NE 800000
#define DI 128
#define HH 256

// -------- scratch (static device globals) --------
__device__ __half g_nfh [(size_t)NN * DI];  // fp16 copy of n_feat
__device__ __half g_h1h [(size_t)NN * HH];  // h1 * outdeg^-1/2, fp16
__device__ __half g_Wst [(size_t)HH * HH];  // [n][k] fp16 of [Wself;Wneigh]
__device__ __half g_W1t [(size_t)HH * HH];  // [n][k] fp16 of W1
__device__ int    g_indeg[NN];
__device__ int    g_outdeg[NN];
__device__ float  g_wsum[NN];
__device__ float  g_m[HH];
__device__ int    g_beg[NN];
__device__ int    g_cursor[NN];
__device__ int    g_csrc[NE];
__device__ int    g_total;

__device__ __forceinline__ float leaky(float x) {
    return (x >= 0.f) ? x : 0.01f * x;
}

__device__ __forceinline__ uint32_t s2u(const void* p) {
    return (uint32_t)__cvta_generic_to_shared(p);
}

__device__ __forceinline__ void red_add_i(int* p, int v) {
    asm volatile("red.global.add.s32 [%0], %1;"
                 :: "l"(__cvta_generic_to_global(p)), "r"(v) : "memory");
}
__device__ __forceinline__ void red_add_f(float* p, float v) {
    asm volatile("red.global.add.f32 [%0], %1;"
                 :: "l"(__cvta_generic_to_global(p)), "f"(v) : "memory");
}

#define LDSM4(r0, r1, r2, r3, addr)                                          \
    asm volatile("ldmatrix.sync.aligned.m8n8.x4.shared.b16 {%0,%1,%2,%3}, [%4];" \
                 : "=r"(r0), "=r"(r1), "=r"(r2), "=r"(r3) : "r"(addr))

__device__ __forceinline__ void mma_f16(float c[4],
    uint32_t a0, uint32_t a1, uint32_t a2, uint32_t a3,
    uint32_t b0, uint32_t b1)
{
    asm volatile(
        "mma.sync.aligned.m16n8k16.row.col.f32.f16.f16.f32 "
        "{%0,%1,%2,%3},{%4,%5,%6,%7},{%8,%9},{%0,%1,%2,%3};"
        : "+f"(c[0]), "+f"(c[1]), "+f"(c[2]), "+f"(c[3])
        : "r"(a0), "r"(a1), "r"(a2), "r"(a3), "r"(b0), "r"(b1));
}

__device__ __forceinline__ void cpa16(uint32_t saddr, const void* g) {
    asm volatile("cp.async.cg.shared.global [%0], [%1], 16;"
                 :: "r"(saddr), "l"(g));
}
#define CPA_COMMIT() asm volatile("cp.async.commit_group;")
#define CPA_WAIT(n)  asm volatile("cp.async.wait_group %0;" :: "n"(n))

// -------- zero per-launch state --------
__global__ void k_zero() {
    int i = blockIdx.x * blockDim.x + threadIdx.x;
    if (i < NN) { g_indeg[i] = 0; g_outdeg[i] = 0; g_wsum[i] = 0.f; }
    if (i < HH) g_m[i] = 0.f;
    if (i == 0) g_total = 0;
}

// -------- fused pre-pass: indeg (red.global) + nf->fp16 + weight transpose --------
__global__ __launch_bounds__(256) void k_pre(
    const int* __restrict__ dst, const float* __restrict__ nf,
    const float* __restrict__ Wself, const float* __restrict__ Wneigh,
    const float* __restrict__ W1)
{
    int i = blockIdx.x * blockDim.x + threadIdx.x;
    if (i < NE) red_add_i(&g_indeg[dst[i]], 1);
    if (i < NN * DI / 2) {
        float2 v = ((const float2*)nf)[i];
        ((__half2*)g_nfh)[i] = __floats2half2_rn(v.x, v.y);
    }
    if (i < HH * HH) {
        int n = i >> 8, k = i & 255;
        float v = (k < DI) ? Wself[k * HH + n] : Wneigh[(k - DI) * HH + n];
        g_Wst[i] = __float2half_rn(v);
        g_W1t[i] = __float2half_rn(W1[k * HH + n]);
    }
}

// -------- assign CSR row bases: warp-scan + one atomic per warp --------
__global__ __launch_bounds__(256) void k_assign() {
    int i = blockIdx.x * blockDim.x + threadIdx.x;
    int lane = threadIdx.x & 31;
    int d = (i < NN) ? g_indeg[i] : 0;
    int x = d;
#pragma unroll
    for (int off = 1; off < 32; off <<= 1) {
        int y = __shfl_up_sync(0xffffffffu, x, off);
        if (lane >= off) x += y;
    }
    int base = 0;
    if (lane == 31) base = atomicAdd(&g_total, x);
    base = __shfl_sync(0xffffffffu, base, 31);
    if (i < NN) {
        int b = base + x - d;
        g_beg[i] = b;
        g_cursor[i] = b;
    }
}

// -------- scatter: CSR fill + outdeg/wsum via red.global --------
__global__ void k_scatter(const int* __restrict__ src, const int* __restrict__ dst) {
    int e = blockIdx.x * blockDim.x + threadIdx.x;
    if (e >= NE) return;
    int s = src[e];
    int d = dst[e];
    red_add_i(&g_outdeg[s], 1);
    red_add_f(&g_wsum[s], rsqrtf((float)g_indeg[d]));
    int pos = atomicAdd(&g_cursor[d], 1);
    g_csrc[pos] = s;
}

// ============ fused agg+GEMM kernels ============
// A smem: 128 rows x 512B (K=256 fp16), 16B seg s of row r at r*512 + ((s^(r&7))<<4).
// B smem: 2 stages x (256 n-rows x 64B), seg c of row n at n*64 + ((c^((n>>1)&3))<<4).
#define A_BYTES 65536
#define B_STAGE 16384
#define FSMEM  (A_BYTES + 2 * B_STAGE)

__device__ __forceinline__ void load_B_stage(
    uint32_t bbase, int t, const __half* __restrict__ Bsrc)
{
#pragma unroll
    for (int i = 0; i < 4; i++) {
        int idx = i * 256 + t;
        int row = idx >> 2;
        int cg  = idx & 3;
        cpa16(bbase + row * 64 + ((cg ^ ((row >> 1) & 3)) << 4),
              Bsrc + (size_t)row * HH + cg * 8);
    }
}

__device__ __forceinline__ void gemm_compute_tile(
    uint32_t asb, uint32_t bbase, int tile, int lane, int wr, int wc,
    float c[4][8][4])
{
#pragma unroll
    for (int ks = 0; ks < 2; ks++) {
        uint32_t a[4][4], b[8][2];
#pragma unroll
        for (int i = 0; i < 4; i++) {
            int rowA = wr * 64 + i * 16 + (lane & 15);
            int segA = tile * 4 + ks * 2 + (lane >> 4);
            uint32_t addr = asb + rowA * 512 + ((segA ^ (rowA & 7)) << 4);
            LDSM4(a[i][0], a[i][1], a[i][2], a[i][3], addr);
        }
#pragma unroll
        for (int p = 0; p < 4; p++) {
            int rowB = wc * 64 + p * 16 + ((lane >> 4) << 3) + (lane & 7);
            int cB = ks * 2 + ((lane >> 3) & 1);
            uint32_t addr = bbase + rowB * 64 + ((cB ^ ((rowB >> 1) & 3)) << 4);
            LDSM4(b[2 * p][0], b[2 * p][1], b[2 * p + 1][0], b[2 * p + 1][1], addr);
        }
#pragma unroll
        for (int i = 0; i < 4; i++)
#pragma unroll
            for (int j = 0; j < 8; j++)
                mma_f16(c[i][j], a[i][0], a[i][1], a[i][2], a[i][3], b[j][0], b[j][1]);
    }
}

// F1: gather SAGE mean into A[:,128:256], copy nf into A[:,0:128], then
//     h1h[r,:] = fp16( leaky(A @ Wst^T + b) * outdeg^-1/2 )
__global__ __launch_bounds__(256, 1) void k_f1(const float* __restrict__ bsage)
{
    extern __shared__ __align__(16) uint8_t smem[];
    const int t = threadIdx.x;
    const int lane = t & 31;
    const int warp = t >> 5;
    const int wr = warp >> 2;
    const int wc = warp & 3;
    const int r4 = lane >> 2;
    const int c4 = lane & 3;
    const int blockRow = blockIdx.x * 128;
    const uint32_t asb = s2u(smem);
    const uint32_t bsb = asb + A_BYTES;

    // prefetch B tile 0 before gathering
    load_B_stage(bsb, t, g_Wst);
    CPA_COMMIT();

    // gather phase: each warp handles 16 rows
    const uint2* nh = (const uint2*)g_nfh;
    for (int rr = 0; rr < 16; rr++) {
        int row = warp * 16 + rr;
        int gr = blockRow + row;
        uint2 nfv = make_uint2(0u, 0u);
        uint2 a1v = make_uint2(0u, 0u);
        if (gr < NN) {
            nfv = nh[(size_t)gr * 32 + lane];
            int beg = g_beg[gr];
            int deg = g_indeg[gr];
            int end = beg + deg;
            float a0 = 0.f, a1 = 0.f, a2 = 0.f, a3 = 0.f;
            int i = beg;
            for (; i + 1 < end; i += 2) {
                int s0 = g_csrc[i];
                int s1 = g_csrc[i + 1];
                uint2 u = nh[(size_t)s0 * 32 + lane];
                uint2 v = nh[(size_t)s1 * 32 + lane];
                float2 f0 = __half22float2(*(__half2*)&u.x);
                float2 f1 = __half22float2(*(__half2*)&u.y);
                float2 g0 = __half22float2(*(__half2*)&v.x);
                float2 g1 = __half22float2(*(__half2*)&v.y);
                a0 += f0.x + g0.x; a1 += f0.y + g0.y;
                a2 += f1.x + g1.x; a3 += f1.y + g1.y;
            }
            if (i < end) {
                int s0 = g_csrc[i];
                uint2 u = nh[(size_t)s0 * 32 + lane];
                float2 f0 = __half22float2(*(__half2*)&u.x);
                float2 f1 = __half22float2(*(__half2*)&u.y);
                a0 += f0.x; a1 += f0.y; a2 += f1.x; a3 += f1.y;
            }
            float inv = (deg > 0) ? 1.f / (float)deg : 0.f;
            __half2 h0 = __floats2half2_rn(a0 * inv, a1 * inv);
            __half2 h1 = __floats2half2_rn(a2 * inv, a3 * inv);
            a1v.x = *(uint32_t*)&h0;
            a1v.y = *(uint32_t*)&h1;
        }
        uint32_t base = asb + row * 512 + (lane & 1) * 8;
        int sg = lane >> 1;
        *(uint2*)(smem + (base - asb) + 0) = nfv, (void)0;  // placeholder avoided below
        // write via swizzled addresses:
        *(uint2*)(smem + row * 512 + (((sg)      ^ (row & 7)) << 4) + (lane & 1) * 8) = nfv;
        *(uint2*)(smem + row * 512 + (((16 + sg) ^ (row & 7)) << 4) + (lane & 1) * 8) = a1v;
    }
    __syncthreads();

    float c[4][8][4];
#pragma unroll
    for (int i = 0; i < 4; i++)
#pragma unroll
        for (int j = 0; j < 8; j++)
#pragma unroll
            for (int q = 0; q < 4; q++) c[i][j][q] = 0.f;

    int cur = 0;
#pragma unroll
    for (int tile = 0; tile < 8; tile++) {
        if (tile + 1 < 8) {
            load_B_stage(bsb + (1 - cur) * B_STAGE, t, g_Wst + (tile + 1) * 32);
            CPA_COMMIT();
            CPA_WAIT(1);
        } else {
            CPA_WAIT(0);
        }
        __syncthreads();
        gemm_compute_tile(asb, bsb + cur * B_STAGE, tile, lane, wr, wc, c);
        __syncthreads();
        cur ^= 1;
    }

#pragma unroll
    for (int i = 0; i < 4; i++) {
        int r0 = blockRow + wr * 64 + i * 16 + r4;
        int r1 = r0 + 8;
        float s0 = (r0 < NN) ? rsqrtf((float)max(g_outdeg[r0], 1)) : 0.f;
        float s1 = (r1 < NN) ? rsqrtf((float)max(g_outdeg[r1], 1)) : 0.f;
#pragma unroll
        for (int j = 0; j < 8; j++) {
            int col = wc * 64 + j * 8 + c4 * 2;
            float bx = bsage[col], by = bsage[col + 1];
            if (r0 < NN) {
                __half2 v = __floats2half2_rn(leaky(c[i][j][0] + bx) * s0,
                                              leaky(c[i][j][1] + by) * s0);
                *(__half2*)(g_h1h + (size_t)r0 * HH + col) = v;
            }
            if (r1 < NN) {
                __half2 v = __floats2half2_rn(leaky(c[i][j][2] + bx) * s1,
                                              leaky(c[i][j][3] + by) * s1);
                *(__half2*)(g_h1h + (size_t)r1 * HH + col) = v;
            }
        }
    }
}

// F2: gather (indeg^-1/2 * sum h1h) into A, then h2 = leaky(A @ W1t^T + b1),
//     g_m += wsum(r)*outdeg^-1/2 * h2[r,:]
__global__ __launch_bounds__(256, 1) void k_f2(const float* __restrict__ b1)
{
    extern __shared__ __align__(16) uint8_t smem[];
    const int t = threadIdx.x;
    const int lane = t & 31;
    const int warp = t >> 5;
    const int wr = warp >> 2;
    const int wc = warp & 3;
    const int r4 = lane >> 2;
    const int c4 = lane & 3;
    const int blockRow = blockIdx.x * 128;
    const uint32_t asb = s2u(smem);
    const uint32_t bsb = asb + A_BYTES;

    load_B_stage(bsb, t, g_W1t);
    CPA_COMMIT();

    const uint2* hh = (const uint2*)g_h1h;
    for (int rr = 0; rr < 16; rr++) {
        int row = warp * 16 + rr;
        int gr = blockRow + row;
        uint2 oa = make_uint2(0u, 0u);
        uint2 ob = make_uint2(0u, 0u);
        if (gr < NN) {
            int beg = g_beg[gr];
            int deg = g_indeg[gr];
            int end = beg + deg;
            float acc[8];
#pragma unroll
            for (int q = 0; q < 8; q++) acc[q] = 0.f;
            int i = beg;
            for (; i + 1 < end; i += 2) {
                int s0 = g_csrc[i];
                int s1 = g_csrc[i + 1];
                uint2 u0a = hh[(size_t)s0 * 64 + lane];
                uint2 u0b = hh[(size_t)s0 * 64 + 32 + lane];
                uint2 u1a = hh[(size_t)s1 * 64 + lane];
                uint2 u1b = hh[(size_t)s1 * 64 + 32 + lane];
                float2 f;
                f = __half22float2(*(__half2*)&u0a.x); acc[0] += f.x; acc[1] += f.y;
                f = __half22float2(*(__half2*)&u0a.y); acc[2] += f.x; acc[3] += f.y;
                f = __half22float2(*(__half2*)&u0b.x); acc[4] += f.x; acc[5] += f.y;
                f = __half22float2(*(__half2*)&u0b.y); acc[6] += f.x; acc[7] += f.y;
                f = __half22float2(*(__half2*)&u1a.x); acc[0] += f.x; acc[1] += f.y;
                f = __half22float2(*(__half2*)&u1a.y); acc[2] += f.x; acc[3] += f.y;
                f = __half22float2(*(__half2*)&u1b.x); acc[4] += f.x; acc[5] += f.y;
                f = __half22float2(*(__half2*)&u1b.y); acc[6] += f.x; acc[7] += f.y;
            }
            if (i < end) {
                int s0 = g_csrc[i];
                uint2 ua = hh[(size_t)s0 * 64 + lane];
                uint2 ub = hh[(size_t)s0 * 64 + 32 + lane];
                float2 f;
                f = __half22float2(*(__half2*)&ua.x); acc[0] += f.x; acc[1] += f.y;
                f = __half22float2(*(__half2*)&ua.y); acc[2] += f.x; acc[3] += f.y;
                f = __half22float2(*(__half2*)&ub.x); acc[4] += f.x; acc[5] += f.y;
                f = __half22float2(*(__half2*)&ub.y); acc[6] += f.x; acc[7] += f.y;
            }
            float sc = rsqrtf((float)max(deg, 1));
            __half2 h0 = __floats2half2_rn(acc[0] * sc, acc[1] * sc);
            __half2 h1 = __floats2half2_rn(acc[2] * sc, acc[3] * sc);
            __half2 h2 = __floats2half2_rn(acc[4] * sc, acc[5] * sc);
            __half2 h3 = __floats2half2_rn(acc[6] * sc, acc[7] * sc);
            oa.x = *(uint32_t*)&h0; oa.y = *(uint32_t*)&h1;
            ob.x = *(uint32_t*)&h2; ob.y = *(uint32_t*)&h3;
        }
        int sg = lane >> 1;
        *(uint2*)(smem + row * 512 + (((sg)      ^ (row & 7)) << 4) + (lane & 1) * 8) = oa;
        *(uint2*)(smem + row * 512 + (((16 + sg) ^ (row & 7)) << 4) + (lane & 1) * 8) = ob;
    }
    __syncthreads();

    float c[4][8][4];
#pragma unroll
    for (int i = 0; i < 4; i++)
#pragma unroll
        for (int j = 0; j < 8; j++)
#pragma unroll
            for (int q = 0; q < 4; q++) c[i][j][q] = 0.f;

    int cur = 0;
#pragma unroll
    for (int tile = 0; tile < 8; tile++) {
        if (tile + 1 < 8) {
            load_B_stage(bsb + (1 - cur) * B_STAGE, t, g_W1t + (tile + 1) * 32);
            CPA_COMMIT();
            CPA_WAIT(1);
        } else {
            CPA_WAIT(0);
        }
        __syncthreads();
        gemm_compute_tile(asb, bsb + cur * B_STAGE, tile, lane, wr, wc, c);
        __syncthreads();
        cur ^= 1;
    }

    // fused epilogue: weighted column sums into g_m (colacc overlays A smem)
    float* colacc = (float*)smem;
    colacc[t] = 0.f;
    __syncthreads();

    float w0v[4], w1v[4];
#pragma unroll
    for (int i = 0; i < 4; i++) {
        int r0 = blockRow + wr * 64 + i * 16 + r4;
        int r1 = r0 + 8;
        w0v[i] = (r0 < NN) ? g_wsum[r0] * rsqrtf((float)max(g_outdeg[r0], 1)) : 0.f;
        w1v[i] = (r1 < NN) ? g_wsum[r1] * rsqrtf((float)max(g_outdeg[r1], 1)) : 0.f;
    }
#pragma unroll
    for (int j = 0; j < 8; j++) {
        int col = wc * 64 + j * 8 + c4 * 2;
        float bx = b1[col], by = b1[col + 1];
        float accLo = 0.f, accHi = 0.f;
#pragma unroll
        for (int i = 0; i < 4; i++) {
            accLo += w0v[i] * leaky(c[i][j][0] + bx) + w1v[i] * leaky(c[i][j][2] + bx);
            accHi += w0v[i] * leaky(c[i][j][1] + by) + w1v[i] * leaky(c[i][j][3] + by);
        }
        atomicAdd(&colacc[col], accLo);
        atomicAdd(&colacc[col + 1], accHi);
    }
    __syncthreads();
    red_add_f(&g_m[t], colacc[t]);
}

// -------- tiny head: out = (g_m/N) @ {Wo,Wd} + {bo,bd} --------
__global__ void k_head(const float* __restrict__ Wo, const float* __restrict__ bo,
                       const float* __restrict__ Wd, const float* __restrict__ bd,
                       float* __restrict__ out, int out_size)
{
    int j = threadIdx.x;
    if (j >= out_size) return;
    const float invN = 1.0f / (float)NN;
    if (j < 100) {
        float acc = 0.f;
        for (int k = 0; k < HH; k++) acc += g_m[k] * Wo[k * 100 + j];
        out[j] = acc * invN + bo[j];
    } else if (j < 108) {
        int jj = j - 100;
        float acc = 0.f;
        for (int k = 0; k < HH; k++) acc += g_m[k] * Wd[k * 8 + jj];
        out[j] = acc * invN + bd[jj];
    }
}

extern "C" void kernel_launch(void* const* d_in, const int* in_sizes, int n_in,
                              void* d_out, int out_size)
{
    const float* n_feat  = (const float*)d_in[0];
    const int*   src     = (const int*)  d_in[1];
    const int*   dst     = (const int*)  d_in[2];
    const float* W_self  = (const float*)d_in[3];
    const float* W_neigh = (const float*)d_in[4];
    const float* b_sage  = (const float*)d_in[5];
    const float* W1      = (const float*)d_in[6];
    const float* b1      = (const float*)d_in[7];
    const float* Wo      = (const float*)d_in[8];
    const float* bo      = (const float*)d_in[9];
    const float* Wd      = (const float*)d_in[10];
    const float* bd      = (const float*)d_in[11];
    float* out = (float*)d_out;

    static bool attr_set = false;
    if (!attr_set) {
        cudaFuncSetAttribute(k_f1, cudaFuncAttributeMaxDynamicSharedMemorySize, FSMEM);
        cudaFuncSetAttribute(k_f2, cudaFuncAttributeMaxDynamicSharedMemorySize, FSMEM);
        attr_set = true;
    }

    k_zero<<<(NN + 255) / 256, 256>>>();
    k_pre<<<(NN * DI / 2 + 255) / 256, 256>>>(dst, n_feat, W_self, W_neigh, W1);
    k_assign<<<(NN + 255) / 256, 256>>>();
    k_scatter<<<(NE + 255) / 256, 256>>>(src, dst);
    k_f1<<<(NN + 127) / 128, 256, FSMEM>>>(b_sage);
    k_f2<<<(NN + 127) / 128, 256, FSMEM>>>(b1);
    k_head<<<1, 128>>>(Wo, bo, Wd, bd, out, out_size);
}

// round 14
// speedup vs baseline: 1.5031x; 1.5031x over previous
#include <cuda_runtime.h>
#include <cuda_fp16.h>
#include <cstdint>

#define NN 50000
#define NE 800000
#define DI 128
#define HH 256

// -------- scratch (static device globals) --------
__device__ __half g_nfh [(size_t)NN * DI];
__device__ __half g_a1h [(size_t)NN * DI];
__device__ __half g_h1h [(size_t)NN * HH];
__device__ __half g_a2h [(size_t)NN * HH];
__device__ __half g_Wst [(size_t)HH * HH];  // [n][k] fp16 of [Wself;Wneigh]
__device__ __half g_W1t [(size_t)HH * HH];  // [n][k] fp16 of W1
__device__ int    g_indeg[NN];
__device__ int    g_outdeg[NN];
__device__ float  g_wsum[NN];
__device__ float  g_m[HH];
__device__ int    g_beg[NN];
__device__ int    g_cursor[NN];
__device__ int    g_csrc[NE];
__device__ int    g_total;

__device__ __forceinline__ float leaky(float x) {
    return (x >= 0.f) ? x : 0.01f * x;
}

__device__ __forceinline__ uint32_t s2u(const void* p) {
    return (uint32_t)__cvta_generic_to_shared(p);
}

__device__ __forceinline__ void red_add_i(int* p, int v) {
    asm volatile("red.global.add.s32 [%0], %1;"
                 :: "l"(__cvta_generic_to_global(p)), "r"(v) : "memory");
}
__device__ __forceinline__ void red_add_f(float* p, float v) {
    asm volatile("red.global.add.f32 [%0], %1;"
                 :: "l"(__cvta_generic_to_global(p)), "f"(v) : "memory");
}

#define LDSM4(r0, r1, r2, r3, addr)                                          \
    asm volatile("ldmatrix.sync.aligned.m8n8.x4.shared.b16 {%0,%1,%2,%3}, [%4];" \
                 : "=r"(r0), "=r"(r1), "=r"(r2), "=r"(r3) : "r"(addr))

__device__ __forceinline__ void mma_f16(float c[4],
    uint32_t a0, uint32_t a1, uint32_t a2, uint32_t a3,
    uint32_t b0, uint32_t b1)
{
    asm volatile(
        "mma.sync.aligned.m16n8k16.row.col.f32.f16.f16.f32 "
        "{%0,%1,%2,%3},{%4,%5,%6,%7},{%8,%9},{%0,%1,%2,%3};"
        : "+f"(c[0]), "+f"(c[1]), "+f"(c[2]), "+f"(c[3])
        : "r"(a0), "r"(a1), "r"(a2), "r"(a3), "r"(b0), "r"(b1));
}

__device__ __forceinline__ void cpa16(uint32_t saddr, const void* g, int src_bytes) {
    asm volatile("cp.async.cg.shared.global [%0], [%1], 16, %2;"
                 :: "r"(saddr), "l"(g), "r"(src_bytes));
}
#define CPA_COMMIT() asm volatile("cp.async.commit_group;")
#define CPA_WAIT(n)  asm volatile("cp.async.wait_group %0;" :: "n"(n))

// -------- zero per-launch state --------
__global__ void k_zero() {
    int i = blockIdx.x * blockDim.x + threadIdx.x;
    if (i < NN) { g_indeg[i] = 0; g_outdeg[i] = 0; g_wsum[i] = 0.f; }
    if (i < HH) g_m[i] = 0.f;
    if (i == 0) g_total = 0;
}

// -------- fused pre-pass: indeg (red.global) + nf->fp16 + weight transpose --------
__global__ __launch_bounds__(256) void k_pre(
    const int* __restrict__ dst, const float* __restrict__ nf,
    const float* __restrict__ Wself, const float* __restrict__ Wneigh,
    const float* __restrict__ W1)
{
    int i = blockIdx.x * blockDim.x + threadIdx.x;
    if (i < NE) red_add_i(&g_indeg[dst[i]], 1);
    if (i < NN * DI / 2) {
        float2 v = ((const float2*)nf)[i];
        ((__half2*)g_nfh)[i] = __floats2half2_rn(v.x, v.y);
    }
    if (i < HH * HH) {
        int n = i >> 8, k = i & 255;
        float v = (k < DI) ? Wself[k * HH + n] : Wneigh[(k - DI) * HH + n];
        g_Wst[i] = __float2half_rn(v);
        g_W1t[i] = __float2half_rn(W1[k * HH + n]);
    }
}

// -------- assign CSR row bases: warp-scan + one atomic per warp --------
__global__ __launch_bounds__(256) void k_assign() {
    int i = blockIdx.x * blockDim.x + threadIdx.x;
    int lane = threadIdx.x & 31;
    int d = (i < NN) ? g_indeg[i] : 0;
    int x = d;
#pragma unroll
    for (int off = 1; off < 32; off <<= 1) {
        int y = __shfl_up_sync(0xffffffffu, x, off);
        if (lane >= off) x += y;
    }
    int base = 0;
    if (lane == 31) base = atomicAdd(&g_total, x);
    base = __shfl_sync(0xffffffffu, base, 31);
    if (i < NN) {
        int b = base + x - d;
        g_beg[i] = b;
        g_cursor[i] = b;
    }
}

// -------- scatter: CSR fill (atomic return) + outdeg/wsum via red.global --------
__global__ void k_scatter(const int* __restrict__ src, const int* __restrict__ dst) {
    int e = blockIdx.x * blockDim.x + threadIdx.x;
    if (e >= NE) return;
    int s = src[e];
    int d = dst[e];
    red_add_i(&g_outdeg[s], 1);
    red_add_f(&g_wsum[s], rsqrtf((float)g_indeg[d]));
    int pos = atomicAdd(&g_cursor[d], 1);
    g_csrc[pos] = s;
}

// -------- SAGE neighbor MEAN aggregation: warp/node, fp16 gather --------
__global__ __launch_bounds__(256) void k_agg1() {
    int w = (blockIdx.x * blockDim.x + threadIdx.x) >> 5;
    if (w >= NN) return;
    int lane = threadIdx.x & 31;
    int beg = g_beg[w];
    int deg = g_indeg[w];
    int end = beg + deg;
    const uint2* nh = (const uint2*)g_nfh;
    float a0 = 0.f, a1 = 0.f, a2 = 0.f, a3 = 0.f;
    int i = beg;
    for (; i + 1 < end; i += 2) {
        int s0 = __ldg(&g_csrc[i]);
        int s1 = __ldg(&g_csrc[i + 1]);
        uint2 u = __ldg(&nh[(size_t)s0 * 32 + lane]);
        uint2 v = __ldg(&nh[(size_t)s1 * 32 + lane]);
        float2 f0 = __half22float2(*(__half2*)&u.x);
        float2 f1 = __half22float2(*(__half2*)&u.y);
        float2 g0 = __half22float2(*(__half2*)&v.x);
        float2 g1 = __half22float2(*(__half2*)&v.y);
        a0 += f0.x + g0.x; a1 += f0.y + g0.y;
        a2 += f1.x + g1.x; a3 += f1.y + g1.y;
    }
    if (i < end) {
        int s0 = __ldg(&g_csrc[i]);
        uint2 u = __ldg(&nh[(size_t)s0 * 32 + lane]);
        float2 f0 = __half22float2(*(__half2*)&u.x);
        float2 f1 = __half22float2(*(__half2*)&u.y);
        a0 += f0.x; a1 += f0.y; a2 += f1.x; a3 += f1.y;
    }
    float inv = (deg > 0) ? 1.f / (float)deg : 0.f;
    __half2 h0 = __floats2half2_rn(a0 * inv, a1 * inv);
    __half2 h1 = __floats2half2_rn(a2 * inv, a3 * inv);
    uint2 o;
    o.x = *(uint32_t*)&h0;
    o.y = *(uint32_t*)&h1;
    ((uint2*)g_a1h)[(size_t)w * 32 + lane] = o;
}

// -------- layer-2 aggregation: warp/node, uint4 (16B/lane covers full 512B row) --------
__global__ __launch_bounds__(256) void k_agg2() {
    int w = (blockIdx.x * blockDim.x + threadIdx.x) >> 5;
    if (w >= NN) return;
    int lane = threadIdx.x & 31;
    int beg = g_beg[w];
    int deg = g_indeg[w];
    int end = beg + deg;
    const uint4* hh = (const uint4*)g_h1h;   // 8 halves per uint4; 32 per row
    float acc[8];
#pragma unroll
    for (int q = 0; q < 8; q++) acc[q] = 0.f;
    int i = beg;
    for (; i + 1 < end; i += 2) {
        int s0 = __ldg(&g_csrc[i]);
        int s1 = __ldg(&g_csrc[i + 1]);
        uint4 u = __ldg(&hh[(size_t)s0 * 32 + lane]);
        uint4 v = __ldg(&hh[(size_t)s1 * 32 + lane]);
        const uint32_t* up = &u.x;
        const uint32_t* vp = &v.x;
#pragma unroll
        for (int q = 0; q < 4; q++) {
            float2 fu = __half22float2(*(__half2*)&up[q]);
            float2 fv = __half22float2(*(__half2*)&vp[q]);
            acc[2 * q]     += fu.x + fv.x;
            acc[2 * q + 1] += fu.y + fv.y;
        }
    }
    if (i < end) {
        int s0 = __ldg(&g_csrc[i]);
        uint4 u = __ldg(&hh[(size_t)s0 * 32 + lane]);
        const uint32_t* up = &u.x;
#pragma unroll
        for (int q = 0; q < 4; q++) {
            float2 fu = __half22float2(*(__half2*)&up[q]);
            acc[2 * q]     += fu.x;
            acc[2 * q + 1] += fu.y;
        }
    }
    float sc = rsqrtf((float)max(deg, 1));
    uint4 o;
    uint32_t* op = &o.x;
#pragma unroll
    for (int q = 0; q < 4; q++) {
        __half2 h = __floats2half2_rn(acc[2 * q] * sc, acc[2 * q + 1] * sc);
        op[q] = *(uint32_t*)&h;
    }
    ((uint4*)g_a2h)[(size_t)w * 32 + lane] = o;
}

// ============ fp16 GEMM, 128x128 tile, BK=32, cp.async double-buffered ============
// grid.y selects N-half. 2 CTAs/SM.
#define A_STAGE 8192
#define B_STAGE 8192

__device__ __forceinline__ void gemm_load_stage(
    uint32_t asb, uint32_t bsb, int stage, int t, int blockRow,
    const __half* __restrict__ Asrc, int aStride, const __half* __restrict__ Bsrc)
{
    uint32_t abase = asb + stage * A_STAGE;
    uint32_t bbase = bsb + stage * B_STAGE;
#pragma unroll
    for (int i = 0; i < 2; i++) {
        int idx = i * 256 + t;
        int row = idx >> 2;
        int cg  = idx & 3;
        int gr  = blockRow + row;
        int ok  = (gr < NN);
        int grc = ok ? gr : (NN - 1);
        cpa16(abase + row * 64 + ((cg ^ ((row >> 1) & 3)) << 4),
              Asrc + (size_t)grc * aStride + cg * 8, ok ? 16 : 0);
    }
#pragma unroll
    for (int i = 0; i < 2; i++) {
        int idx = i * 256 + t;
        int row = idx >> 2;      // n within 128
        int cg  = idx & 3;
        cpa16(bbase + row * 64 + ((cg ^ ((row >> 1) & 3)) << 4),
              Bsrc + (size_t)row * HH + cg * 8, 16);
    }
}

__device__ __forceinline__ void gemm_compute_stage(
    uint32_t asb, uint32_t bsb, int stage, int lane, int wr, int wc,
    float c[4][4][4])
{
    uint32_t abase = asb + stage * A_STAGE;
    uint32_t bbase = bsb + stage * B_STAGE;
#pragma unroll
    for (int ks = 0; ks < 2; ks++) {
        uint32_t a[4][4], b[4][2];
#pragma unroll
        for (int i = 0; i < 4; i++) {
            int rowA = wr * 64 + i * 16 + (lane & 15);
            int cA = ks * 2 + (lane >> 4);
            uint32_t addr = abase + rowA * 64 + ((cA ^ ((rowA >> 1) & 3)) << 4);
            LDSM4(a[i][0], a[i][1], a[i][2], a[i][3], addr);
        }
#pragma unroll
        for (int p = 0; p < 2; p++) {
            int rowB = wc * 32 + p * 16 + ((lane >> 4) << 3) + (lane & 7);
            int cB = ks * 2 + ((lane >> 3) & 1);
            uint32_t addr = bbase + rowB * 64 + ((cB ^ ((rowB >> 1) & 3)) << 4);
            LDSM4(b[2 * p][0], b[2 * p][1], b[2 * p + 1][0], b[2 * p + 1][1], addr);
        }
#pragma unroll
        for (int i = 0; i < 4; i++)
#pragma unroll
            for (int j = 0; j < 4; j++)
                mma_f16(c[i][j], a[i][0], a[i][1], a[i][2], a[i][3], b[j][0], b[j][1]);
    }
}

// GEMM1: h1h[r, n0:+128] = fp16( leaky([nfh|a1h][r,:] @ Wst^T + b) * outdeg^-1/2 )
__global__ __launch_bounds__(256, 2) void k_gemm1(const float* __restrict__ bsage)
{
    __shared__ __align__(16) uint8_t AsB[2 * A_STAGE];
    __shared__ __align__(16) uint8_t BsB[2 * B_STAGE];
    const int t = threadIdx.x;
    const int lane = t & 31;
    const int warp = t >> 5;
    const int wr = warp >> 2;
    const int wc = warp & 3;
    const int r4 = lane >> 2;
    const int c4 = lane & 3;
    const int blockRow = blockIdx.x * 128;
    const int n0 = blockIdx.y * 128;
    const __half* Wt = g_Wst + (size_t)n0 * HH;
    const uint32_t asb = s2u(AsB);
    const uint32_t bsb = s2u(BsB);

    float c[4][4][4];
#pragma unroll
    for (int i = 0; i < 4; i++)
#pragma unroll
        for (int j = 0; j < 4; j++)
#pragma unroll
            for (int q = 0; q < 4; q++) c[i][j][q] = 0.f;

    gemm_load_stage(asb, bsb, 0, t, blockRow, g_nfh, DI, Wt);
    CPA_COMMIT();
    int cur = 0;
#pragma unroll
    for (int tile = 0; tile < 8; tile++) {
        if (tile + 1 < 8) {
            int nt = tile + 1;
            const __half* Asrc = (nt < 4) ? (g_nfh + nt * 32) : (g_a1h + (nt - 4) * 32);
            gemm_load_stage(asb, bsb, 1 - cur, t, blockRow, Asrc, DI, Wt + nt * 32);
            CPA_COMMIT();
            CPA_WAIT(1);
        } else {
            CPA_WAIT(0);
        }
        __syncthreads();
        gemm_compute_stage(asb, bsb, cur, lane, wr, wc, c);
        __syncthreads();
        cur ^= 1;
    }

#pragma unroll
    for (int i = 0; i < 4; i++) {
        int r0 = blockRow + wr * 64 + i * 16 + r4;
        int r1 = r0 + 8;
        float s0 = (r0 < NN) ? rsqrtf((float)max(g_outdeg[r0], 1)) : 0.f;
        float s1 = (r1 < NN) ? rsqrtf((float)max(g_outdeg[r1], 1)) : 0.f;
#pragma unroll
        for (int j = 0; j < 4; j++) {
            int col = n0 + wc * 32 + j * 8 + c4 * 2;
            float bx = bsage[col], by = bsage[col + 1];
            if (r0 < NN) {
                __half2 v = __floats2half2_rn(leaky(c[i][j][0] + bx) * s0,
                                              leaky(c[i][j][1] + by) * s0);
                *(__half2*)(g_h1h + (size_t)r0 * HH + col) = v;
            }
            if (r1 < NN) {
                __half2 v = __floats2half2_rn(leaky(c[i][j][2] + bx) * s1,
                                              leaky(c[i][j][3] + by) * s1);
                *(__half2*)(g_h1h + (size_t)r1 * HH + col) = v;
            }
        }
    }
}

// GEMM2: h2[r,:] = leaky(a2h[r,:] @ W1t^T + b1);  g_m[:] += w(r) * h2[r,:]
__global__ __launch_bounds__(256, 2) void k_gemm2(const float* __restrict__ b1)
{
    __shared__ __align__(16) uint8_t AsB[2 * A_STAGE];
    __shared__ __align__(16) uint8_t BsB[2 * B_STAGE];
    const int t = threadIdx.x;
    const int lane = t & 31;
    const int warp = t >> 5;
    const int wr = warp >> 2;
    const int wc = warp & 3;
    const int r4 = lane >> 2;
    const int c4 = lane & 3;
    const int blockRow = blockIdx.x * 128;
    const int n0 = blockIdx.y * 128;
    const __half* Wt = g_W1t + (size_t)n0 * HH;
    const uint32_t asb = s2u(AsB);
    const uint32_t bsb = s2u(BsB);

    float c[4][4][4];
#pragma unroll
    for (int i = 0; i < 4; i++)
#pragma unroll
        for (int j = 0; j < 4; j++)
#pragma unroll
            for (int q = 0; q < 4; q++) c[i][j][q] = 0.f;

    gemm_load_stage(asb, bsb, 0, t, blockRow, g_a2h, HH, Wt);
    CPA_COMMIT();
    int cur = 0;
#pragma unroll
    for (int tile = 0; tile < 8; tile++) {
        if (tile + 1 < 8) {
            int nt = tile + 1;
            gemm_load_stage(asb, bsb, 1 - cur, t, blockRow, g_a2h + nt * 32, HH,
                            Wt + nt * 32);
            CPA_COMMIT();
            CPA_WAIT(1);
        } else {
            CPA_WAIT(0);
        }
        __syncthreads();
        gemm_compute_stage(asb, bsb, cur, lane, wr, wc, c);
        __syncthreads();
        cur ^= 1;
    }

    // fused epilogue: weighted column sums into g_m (colacc overlays AsB)
    float* colacc = (float*)AsB;
    if (t < 128) colacc[t] = 0.f;
    __syncthreads();

    float w0v[4], w1v[4];
#pragma unroll
    for (int i = 0; i < 4; i++) {
        int r0 = blockRow + wr * 64 + i * 16 + r4;
        int r1 = r0 + 8;
        w0v[i] = (r0 < NN) ? g_wsum[r0] * rsqrtf((float)max(g_outdeg[r0], 1)) : 0.f;
        w1v[i] = (r1 < NN) ? g_wsum[r1] * rsqrtf((float)max(g_outdeg[r1], 1)) : 0.f;
    }
#pragma unroll
    for (int j = 0; j < 4; j++) {
        int lc = wc * 32 + j * 8 + c4 * 2;   // col within 128
        float bx = b1[n0 + lc], by = b1[n0 + lc + 1];
        float accLo = 0.f, accHi = 0.f;
#pragma unroll
        for (int i = 0; i < 4; i++) {
            accLo += w0v[i] * leaky(c[i][j][0] + bx) + w1v[i] * leaky(c[i][j][2] + bx);
            accHi += w0v[i] * leaky(c[i][j][1] + by) + w1v[i] * leaky(c[i][j][3] + by);
        }
        atomicAdd(&colacc[lc], accLo);
        atomicAdd(&colacc[lc + 1], accHi);
    }
    __syncthreads();
    if (t < 128) red_add_f(&g_m[n0 + t], colacc[t]);
}

// -------- tiny head: out = (g_m/N) @ {Wo,Wd} + {bo,bd} --------
__global__ void k_head(const float* __restrict__ Wo, const float* __restrict__ bo,
                       const float* __restrict__ Wd, const float* __restrict__ bd,
                       float* __restrict__ out, int out_size)
{
    int j = threadIdx.x;
    if (j >= out_size) return;
    const float invN = 1.0f / (float)NN;
    if (j < 100) {
        float acc = 0.f;
        for (int k = 0; k < HH; k++) acc += g_m[k] * Wo[k * 100 + j];
        out[j] = acc * invN + bo[j];
    } else if (j < 108) {
        int jj = j - 100;
        float acc = 0.f;
        for (int k = 0; k < HH; k++) acc += g_m[k] * Wd[k * 8 + jj];
        out[j] = acc * invN + bd[jj];
    }
}

extern "C" void kernel_launch(void* const* d_in, const int* in_sizes, int n_in,
                              void* d_out, int out_size)
{
    const float* n_feat  = (const float*)d_in[0];
    const int*   src     = (const int*)  d_in[1];
    const int*   dst     = (const int*)  d_in[2];
    const float* W_self  = (const float*)d_in[3];
    const float* W_neigh = (const float*)d_in[4];
    const float* b_sage  = (const float*)d_in[5];
    const float* W1      = (const float*)d_in[6];
    const float* b1      = (const float*)d_in[7];
    const float* Wo      = (const float*)d_in[8];
    const float* bo      = (const float*)d_in[9];
    const float* Wd      = (const float*)d_in[10];
    const float* bd      = (const float*)d_in[11];
    float* out = (float*)d_out;

    dim3 ggrid((NN + 127) / 128, 2);

    k_zero<<<(NN + 255) / 256, 256>>>();
    k_pre<<<(NN * DI / 2 + 255) / 256, 256>>>(dst, n_feat, W_self, W_neigh, W1);
    k_assign<<<(NN + 255) / 256, 256>>>();
    k_scatter<<<(NE + 255) / 256, 256>>>(src, dst);
    k_agg1<<<(NN * 32 + 255) / 256, 256>>>();
    k_gemm1<<<ggrid, 256>>>(b_sage);
    k_agg2<<<(NN * 32 + 255) / 256, 256>>>();
    k_gemm2<<<ggrid, 256>>>(b1);
    k_head<<<1, 128>>>(Wo, bo, Wd, bd, out, out_size);
}